// round 14
// baseline (speedup 1.0000x reference)
#include <cuda_runtime.h>
#include <cuda_bf16.h>
#include <cstdint>
#include <cstddef>

typedef unsigned long long ull;

#define BATCH 8
#define NTOK  4096
#define DIM   64
#define BM    128
#define BN    64
#define KITER (NTOK / BN)
#define AT    128
#define PT    192

// ---------------- device scratch ----------------
__device__ __nv_bfloat16 g_qh[BATCH * NTOK * DIM];  // [b][n][d] hi
__device__ __nv_bfloat16 g_ql[BATCH * NTOK * DIM];
__device__ __nv_bfloat16 g_kh[BATCH * NTOK * DIM];
__device__ __nv_bfloat16 g_kl[BATCH * NTOK * DIM];
__device__ __nv_bfloat16 g_vh[BATCH * NTOK * DIM];
__device__ __nv_bfloat16 g_vl[BATCH * NTOK * DIM];
__device__ unsigned      g_adjb[NTOK * (NTOK / 32)];

// ---------------- helpers ----------------
__device__ __forceinline__ uint32_t s2u(const void* p) {
    return (uint32_t)__cvta_generic_to_shared(p);
}
__device__ __forceinline__ void cpa16(uint32_t dst, const void* src) {
    asm volatile("cp.async.cg.shared.global [%0], [%1], 16;" :: "r"(dst), "l"(src));
}
#define CP_COMMIT() asm volatile("cp.async.commit_group;")
#define CP_WAIT(n)  asm volatile("cp.async.wait_group %0;" :: "n"(n))
__device__ __forceinline__ float ex2f(float x) {
    float r; asm("ex2.approx.ftz.f32 %0, %1;" : "=f"(r) : "f"(x)); return r;
}
__device__ __forceinline__ void mma16816(float* d, const uint32_t* a, const uint32_t* b) {
    asm volatile("mma.sync.aligned.m16n8k16.row.col.f32.bf16.bf16.f32 "
        "{%0,%1,%2,%3}, {%4,%5,%6,%7}, {%8,%9}, {%0,%1,%2,%3};"
        : "+f"(d[0]), "+f"(d[1]), "+f"(d[2]), "+f"(d[3])
        : "r"(a[0]), "r"(a[1]), "r"(a[2]), "r"(a[3]), "r"(b[0]), "r"(b[1]));
}
__device__ __forceinline__ void ldsm4(uint32_t* r, uint32_t a) {
    asm volatile("ldmatrix.sync.aligned.m8n8.x4.shared.b16 {%0,%1,%2,%3}, [%4];"
        : "=r"(r[0]), "=r"(r[1]), "=r"(r[2]), "=r"(r[3]) : "r"(a));
}
__device__ __forceinline__ void ldsm4t(uint32_t* r, uint32_t a) {
    asm volatile("ldmatrix.sync.aligned.m8n8.x4.trans.shared.b16 {%0,%1,%2,%3}, [%4];"
        : "=r"(r[0]), "=r"(r[1]), "=r"(r[2]), "=r"(r[3]) : "r"(a));
}
__device__ __forceinline__ uint32_t packbf(float f0, float f1) {
    __nv_bfloat16 h0 = __float2bfloat16_rn(f0);
    __nv_bfloat16 h1 = __float2bfloat16_rn(f1);
    return (uint32_t)__bfloat16_as_ushort(h0) | ((uint32_t)__bfloat16_as_ushort(h1) << 16);
}
// pack two floats to bf16x2 (satfinite); low = p0, high = p1
__device__ __forceinline__ uint32_t cvtbf2(float p0, float p1) {
    uint32_t r;
    asm("cvt.rn.satfinite.bf16x2.f32 %0, %1, %2;" : "=r"(r) : "f"(p1), "f"(p0));
    return r;
}

// ---------------- adjacency bit-pack ----------------
__global__ void pack_adj_kernel(const int* __restrict__ A) {
    int gtid = blockIdx.x * blockDim.x + threadIdx.x;
    int gw   = gtid >> 5;
    int lane = gtid & 31;
    int wb   = gw * 32;
    if (wb >= NTOK * (NTOK / 32)) return;
    int row   = wb >> 7;
    int wcol0 = wb & 127;
    const int* ap = A + (size_t)row * NTOK + wcol0 * 32;
    unsigned mine = 0u;
#pragma unroll 8
    for (int k = 0; k < 32; k++) {
        unsigned b = __ballot_sync(0xffffffffu, ap[k * 32 + lane] > 0);
        if (lane == k) mine = b;
    }
    if (wcol0 + lane == (row >> 5)) mine |= 1u << (row & 31);
    g_adjb[wb + lane] = mine;
}

// ---------------- projection kernel -> bf16 split planes [n][d] ----------
#define XS_STR 68
#define PREP_SMEM_FLOATS (64 * XS_STR + 64 * 192)
#define PREP_SMEM_BYTES  (PREP_SMEM_FLOATS * 4)

__global__ __launch_bounds__(PT) void prep_kernel(
    const float* __restrict__ X, const float* __restrict__ W,
    const float* __restrict__ Q, const float* __restrict__ Kp)
{
    extern __shared__ float sm[];
    float* xs = sm;
    float* ws = sm + 64 * XS_STR;
    const int tid = threadIdx.x;
    const int g0  = blockIdx.x * 64;

    for (int idx = tid; idx < 64 * 16; idx += PT) {
        int r = idx >> 4, d4 = (idx & 15) << 2;
        float4 v = *(const float4*)(X + ((size_t)(g0 + r) << 6) + d4);
        xs[(d4 + 0) * XS_STR + r] = v.x;
        xs[(d4 + 1) * XS_STR + r] = v.y;
        xs[(d4 + 2) * XS_STR + r] = v.z;
        xs[(d4 + 3) * XS_STR + r] = v.w;
    }
    for (int idx = tid; idx < 64 * 48; idx += PT) {
        int d = idx / 48;
        int c4 = (idx % 48) << 2;
        const float* src;
        if (c4 < 64)       src = W  + d * 64 + c4;          // -> v
        else if (c4 < 128) src = Q  + d * 64 + (c4 - 64);   // -> q
        else               src = Kp + d * 64 + (c4 - 128);  // -> k
        *(float4*)(ws + d * 192 + c4) = *(const float4*)src;
    }
    __syncthreads();

    const int cg = tid % 24, rg = tid / 24;
    float acc[8][8];
#pragma unroll
    for (int i = 0; i < 8; i++)
#pragma unroll
        for (int j = 0; j < 8; j++) acc[i][j] = 0.f;

#pragma unroll 4
    for (int d = 0; d < 64; d++) {
        float4 a0 = *(const float4*)(xs + d * XS_STR + (rg << 3));
        float4 a1 = *(const float4*)(xs + d * XS_STR + (rg << 3) + 4);
        float4 w0 = *(const float4*)(ws + d * 192 + (cg << 3));
        float4 w1 = *(const float4*)(ws + d * 192 + (cg << 3) + 4);
        float a[8] = {a0.x, a0.y, a0.z, a0.w, a1.x, a1.y, a1.z, a1.w};
        float w[8] = {w0.x, w0.y, w0.z, w0.w, w1.x, w1.y, w1.z, w1.w};
#pragma unroll
        for (int i = 0; i < 8; i++)
#pragma unroll
            for (int j = 0; j < 8; j++) acc[i][j] += a[i] * w[j];
    }

    __nv_bfloat16 *gh, *gl;
    int col0;
    if (cg < 8)       { gh = g_vh; gl = g_vl; col0 = cg << 3; }
    else if (cg < 16) { gh = g_qh; gl = g_ql; col0 = (cg - 8) << 3; }
    else              { gh = g_kh; gl = g_kl; col0 = (cg - 16) << 3; }

#pragma unroll
    for (int i = 0; i < 8; i++) {
        size_t row = (size_t)(g0 + (rg << 3) + i);
        uint32_t hw[4], lw[4];
#pragma unroll
        for (int jp = 0; jp < 4; jp++) {
            float f0 = acc[i][2 * jp], f1 = acc[i][2 * jp + 1];
            __nv_bfloat16 h0 = __float2bfloat16_rn(f0);
            __nv_bfloat16 h1 = __float2bfloat16_rn(f1);
            hw[jp] = (uint32_t)__bfloat16_as_ushort(h0) | ((uint32_t)__bfloat16_as_ushort(h1) << 16);
            lw[jp] = packbf(f0 - __bfloat162float(h0), f1 - __bfloat162float(h1));
        }
        *(uint4*)(gh + row * 64 + col0) = make_uint4(hw[0], hw[1], hw[2], hw[3]);
        *(uint4*)(gl + row * 64 + col0) = make_uint4(lw[0], lw[1], lw[2], lw[3]);
    }
}

// ---------------- mma.sync fused attention ------------------------------
// Double-buffered k/v, one barrier per iteration, fixed-max softmax,
// q fragments hoisted into registers (loaded via ldmatrix ONCE).
#define QH_OFF 0
#define QL_OFF 16384
#define KH_OFF 32768        // 2 x 8KB ring
#define KL_OFF 49152
#define VH_OFF 65536
#define VL_OFF 81920
#define KV_STRIDE 8192
#define ATTN_SMEM_BYTES 98304

__global__ __launch_bounds__(AT, 2) void attn_kernel(float* __restrict__ out) {
    extern __shared__ char smc[];
    const uint32_t sb = s2u(smc);
    const int tid  = threadIdx.x;
    const int warp = tid >> 5;
    const int lane = tid & 31;
    const int q0   = blockIdx.x * BM;
    const int b    = blockIdx.y;

    const __nv_bfloat16* qhb = g_qh + ((size_t)b << 18) + ((size_t)q0 << 6);
    const __nv_bfloat16* qlb = g_ql + ((size_t)b << 18) + ((size_t)q0 << 6);
    const __nv_bfloat16* khb = g_kh + ((size_t)b << 18);
    const __nv_bfloat16* klb = g_kl + ((size_t)b << 18);
    const __nv_bfloat16* vhb = g_vh + ((size_t)b << 18);
    const __nv_bfloat16* vlb = g_vl + ((size_t)b << 18);

    // prologue: q (both planes) + k0/v0 into buffer 0, one group
#pragma unroll
    for (int it = 0; it < 8; it++) {
        int idx = tid + it * AT;           // 0..1023
        int r = idx >> 3, c = idx & 7;
        uint32_t doff = r * 128 + ((c ^ (r & 7)) << 4);
        cpa16(sb + QH_OFF + doff, qhb + r * 64 + c * 8);
        cpa16(sb + QL_OFF + doff, qlb + r * 64 + c * 8);
    }
#pragma unroll
    for (int it = 0; it < 4; it++) {
        int idx = tid + it * AT;           // 0..511
        int r = idx >> 3, c = idx & 7;
        uint32_t doff = r * 128 + ((c ^ (r & 7)) << 4);
        cpa16(sb + KH_OFF + doff, khb + r * 64 + c * 8);
        cpa16(sb + KL_OFF + doff, klb + r * 64 + c * 8);
        cpa16(sb + VH_OFF + doff, vhb + r * 64 + c * 8);
        cpa16(sb + VL_OFF + doff, vlb + r * 64 + c * 8);
    }
    CP_COMMIT();

    // ldmatrix address invariants
    const int lr16 = lane & 15;
    const int lhi  = lane >> 4;            // 0/1
    const int krow_b = (lhi << 3) + (lane & 7);
    const int kchalf = (lane >> 3) & 1;

    // accumulators / state
    float oacc[2][8][4];
    float l4[4];
#pragma unroll
    for (int mt = 0; mt < 2; mt++)
#pragma unroll
        for (int nt = 0; nt < 8; nt++)
#pragma unroll
            for (int e = 0; e < 4; e++) oacc[mt][nt][e] = 0.f;
#pragma unroll
    for (int i = 0; i < 4; i++) l4[i] = 0.f;

    const float L2E = 1.4426950408889634f;
    const float MB  = 88.0f;               // fixed bias (log2 domain)
    const int cb = (lane & 3) << 1;

    CP_WAIT(0);                            // q + k0/v0 resident
    __syncthreads();

    // ---- hoist loop-invariant q fragments into registers (once) ----
    uint32_t uq[2][4][2][4];               // [plane][ks][mt][regs]
#pragma unroll
    for (int ks = 0; ks < 4; ks++)
#pragma unroll
        for (int mt = 0; mt < 2; mt++) {
            int r = (warp << 5) + (mt << 4) + lr16;
            uint32_t ro = (uint32_t)(r * 128);
            uint32_t coff = (uint32_t)(((2 * ks + lhi) ^ (r & 7)) << 4);
            ldsm4(uq[0][ks][mt], sb + QH_OFF + ro + coff);
            ldsm4(uq[1][ks][mt], sb + QL_OFF + ro + coff);
        }

#pragma unroll 1
    for (int kt = 0; kt < KITER; kt++) {
        const uint32_t cur = (uint32_t)(kt & 1) * KV_STRIDE;
        const uint32_t nxt = KV_STRIDE - cur;

        // prefetch k/v[kt+1] into the other buffer (its readers finished
        // before the barrier that ended the previous iteration)
        if (kt + 1 < KITER) {
            const __nv_bfloat16* kh2 = khb + (size_t)(kt + 1) * BN * 64;
            const __nv_bfloat16* kl2 = klb + (size_t)(kt + 1) * BN * 64;
            const __nv_bfloat16* vh2 = vhb + (size_t)(kt + 1) * BN * 64;
            const __nv_bfloat16* vl2 = vlb + (size_t)(kt + 1) * BN * 64;
#pragma unroll
            for (int it = 0; it < 4; it++) {
                int idx = tid + it * AT;
                int r = idx >> 3, c = idx & 7;
                uint32_t doff = r * 128 + ((c ^ (r & 7)) << 4);
                cpa16(sb + KH_OFF + nxt + doff, kh2 + r * 64 + c * 8);
                cpa16(sb + KL_OFF + nxt + doff, kl2 + r * 64 + c * 8);
                cpa16(sb + VH_OFF + nxt + doff, vh2 + r * 64 + c * 8);
                cpa16(sb + VL_OFF + nxt + doff, vl2 + r * 64 + c * 8);
            }
        }
        CP_COMMIT();

        // adjacency words for this tile
        unsigned aw[4][2];
#pragma unroll
        for (int mt = 0; mt < 2; mt++)
#pragma unroll
            for (int dh = 0; dh < 2; dh++) {
                int rg_ = q0 + (warp << 5) + (mt << 4) + (dh << 3) + (lane >> 2);
                const unsigned* ap = g_adjb + ((size_t)rg_ << 7) + (kt << 1);
                aw[mt * 2 + dh][0] = __ldg(ap);
                aw[mt * 2 + dh][1] = __ldg(ap + 1);
            }

        // ---- QK: S = qh*kh + ql*kh + qh*kl (3-pass), q from registers ----
        float sacc[2][8][4];
#pragma unroll
        for (int mt = 0; mt < 2; mt++)
#pragma unroll
            for (int nt = 0; nt < 8; nt++)
#pragma unroll
                for (int e = 0; e < 4; e++) sacc[mt][nt][e] = 0.f;

#pragma unroll
        for (int ks = 0; ks < 4; ks++) {
#pragma unroll
            for (int ntp = 0; ntp < 4; ntp++) {
                int rk = (ntp << 4) + krow_b;
                uint32_t doff = rk * 128 + ((uint32_t)(((2 * ks + kchalf) ^ (rk & 7))) << 4);
                uint32_t bh[4], bl[4];
                ldsm4(bh, sb + KH_OFF + cur + doff);
                ldsm4(bl, sb + KL_OFF + cur + doff);
#pragma unroll
                for (int mt = 0; mt < 2; mt++) {
                    mma16816(sacc[mt][2 * ntp],     uq[0][ks][mt], bh);
                    mma16816(sacc[mt][2 * ntp + 1], uq[0][ks][mt], bh + 2);
                    mma16816(sacc[mt][2 * ntp],     uq[1][ks][mt], bh);
                    mma16816(sacc[mt][2 * ntp + 1], uq[1][ks][mt], bh + 2);
                    mma16816(sacc[mt][2 * ntp],     uq[0][ks][mt], bl);
                    mma16816(sacc[mt][2 * ntp + 1], uq[0][ks][mt], bl + 2);
                }
            }
        }

        // ---- fixed-max softmax: p = 2^(leaky(s)*L2E - MB), masked ----
        uint32_t pha[2][4][4];
#pragma unroll
        for (int mt = 0; mt < 2; mt++)
#pragma unroll
            for (int dh = 0; dh < 2; dh++) {
                const int ri = mt * 2 + dh;
                float rs = 0.f;
#pragma unroll
                for (int nt = 0; nt < 8; nt++) {
                    unsigned w = aw[ri][nt >> 2];
                    const int sh = ((nt & 3) << 3) + cb;
                    float x0 = sacc[mt][nt][(dh << 1)];
                    float x1 = sacc[mt][nt][(dh << 1) + 1];
                    x0 = fmaxf(x0, 0.01f * x0);
                    x1 = fmaxf(x1, 0.01f * x1);
                    float e0 = ex2f(fmaf(x0, L2E, -MB));
                    float e1 = ex2f(fmaf(x1, L2E, -MB));
                    float p0 = ((w >> sh) & 1u)       ? e0 : 0.f;
                    float p1 = ((w >> (sh + 1)) & 1u) ? e1 : 0.f;
                    uint32_t hw = cvtbf2(p0, p1);
                    pha[mt][nt >> 1][(nt & 1) * 2 + dh] = hw;
                    rs += __uint_as_float(hw << 16) + __uint_as_float(hw & 0xffff0000u);
                }
                l4[ri] += rs;
            }

        // ---- PV (2-pass): O += ph*(vh+vl) ----
#pragma unroll
        for (int ks = 0; ks < 4; ks++) {
            int rv = (ks << 4) + lr16;
            uint32_t rbase = rv * 128;
            uint32_t rsw = rv & 7;
#pragma unroll
            for (int ntp = 0; ntp < 4; ntp++) {
                uint32_t coff = ((uint32_t)(((2 * ntp + lhi) ^ rsw)) << 4);
                uint32_t bh[4], bl[4];
                ldsm4t(bh, sb + VH_OFF + cur + rbase + coff);
                ldsm4t(bl, sb + VL_OFF + cur + rbase + coff);
#pragma unroll
                for (int mt = 0; mt < 2; mt++) {
                    mma16816(oacc[mt][2 * ntp],     pha[mt][ks], bh);
                    mma16816(oacc[mt][2 * ntp + 1], pha[mt][ks], bh + 2);
                    mma16816(oacc[mt][2 * ntp],     pha[mt][ks], bl);
                    mma16816(oacc[mt][2 * ntp + 1], pha[mt][ks], bl + 2);
                }
            }
        }

        // wait for next k/v + protect buffer swap
        if (kt + 1 < KITER) {
            CP_WAIT(0);
            __syncthreads();
        }
    }

    // ---- epilogue: reduce l across lane quad ONCE, normalize, store ----
#pragma unroll
    for (int i = 0; i < 4; i++) {
        l4[i] += __shfl_xor_sync(0xffffffffu, l4[i], 1);
        l4[i] += __shfl_xor_sync(0xffffffffu, l4[i], 2);
    }
#pragma unroll
    for (int mt = 0; mt < 2; mt++)
#pragma unroll
        for (int dh = 0; dh < 2; dh++) {
            const int ri = mt * 2 + dh;
            float inv = 1.0f / l4[ri];
            int row_g = q0 + (warp << 5) + (mt << 4) + (dh << 3) + (lane >> 2);
            float* dst = out + ((size_t)(b * NTOK + row_g) << 6) + cb;
#pragma unroll
            for (int nt = 0; nt < 8; nt++) {
                float2 o2 = make_float2(oacc[mt][nt][(dh << 1)] * inv,
                                        oacc[mt][nt][(dh << 1) + 1] * inv);
                *(float2*)(dst + nt * 8) = o2;
            }
        }
}

// ---------------- launch ----------------
extern "C" void kernel_launch(void* const* d_in, const int* in_sizes, int n_in,
                              void* d_out, int out_size) {
    const float* X  = (const float*)d_in[0];
    const int*   A  = (const int*)  d_in[1];
    const float* W  = (const float*)d_in[2];
    const float* Q  = (const float*)d_in[3];
    const float* Kp = (const float*)d_in[4];
    float* out = (float*)d_out;

    cudaFuncSetAttribute(prep_kernel, cudaFuncAttributeMaxDynamicSharedMemorySize, PREP_SMEM_BYTES);
    cudaFuncSetAttribute(attn_kernel, cudaFuncAttributeMaxDynamicSharedMemorySize, ATTN_SMEM_BYTES);

    pack_adj_kernel<<<(NTOK * (NTOK / 32)) / 256, 256>>>(A);
    prep_kernel<<<(BATCH * NTOK) / 64, PT, PREP_SMEM_BYTES>>>(X, W, Q, Kp);
    attn_kernel<<<dim3(NTOK / BM, BATCH), AT, ATTN_SMEM_BYTES>>>(out);
}

// round 15
// speedup vs baseline: 1.5973x; 1.5973x over previous
#include <cuda_runtime.h>
#include <cuda_fp16.h>
#include <cstdint>
#include <cstddef>

typedef unsigned long long ull;

#define BATCH 8
#define NTOK  4096
#define DIM   64
#define BM    128
#define BN    64
#define KITER (NTOK / BN)
#define AT    128
#define PT    192

// ---------------- device scratch ----------------
__device__ __half g_qh[BATCH * NTOK * DIM];  // [b][n][d] hi plane
__device__ __half g_ql[BATCH * NTOK * DIM];  // lo plane
__device__ __half g_kh[BATCH * NTOK * DIM];
__device__ __half g_kl[BATCH * NTOK * DIM];
__device__ __half g_v [BATCH * NTOK * DIM];  // single fp16 plane
__device__ unsigned g_adjb[NTOK * (NTOK / 32)];

// ---------------- helpers ----------------
__device__ __forceinline__ uint32_t s2u(const void* p) {
    return (uint32_t)__cvta_generic_to_shared(p);
}
__device__ __forceinline__ void cpa16(uint32_t dst, const void* src) {
    asm volatile("cp.async.cg.shared.global [%0], [%1], 16;" :: "r"(dst), "l"(src));
}
#define CP_COMMIT() asm volatile("cp.async.commit_group;")
#define CP_WAIT(n)  asm volatile("cp.async.wait_group %0;" :: "n"(n))
__device__ __forceinline__ float ex2f(float x) {
    float r; asm("ex2.approx.ftz.f32 %0, %1;" : "=f"(r) : "f"(x)); return r;
}
// fp16 mma m16n8k16, f32 accumulate
__device__ __forceinline__ void mma16816(float* d, const uint32_t* a, const uint32_t* b) {
    asm volatile("mma.sync.aligned.m16n8k16.row.col.f32.f16.f16.f32 "
        "{%0,%1,%2,%3}, {%4,%5,%6,%7}, {%8,%9}, {%0,%1,%2,%3};"
        : "+f"(d[0]), "+f"(d[1]), "+f"(d[2]), "+f"(d[3])
        : "r"(a[0]), "r"(a[1]), "r"(a[2]), "r"(a[3]), "r"(b[0]), "r"(b[1]));
}
__device__ __forceinline__ void ldsm4(uint32_t* r, uint32_t a) {
    asm volatile("ldmatrix.sync.aligned.m8n8.x4.shared.b16 {%0,%1,%2,%3}, [%4];"
        : "=r"(r[0]), "=r"(r[1]), "=r"(r[2]), "=r"(r[3]) : "r"(a));
}
__device__ __forceinline__ void ldsm4t(uint32_t* r, uint32_t a) {
    asm volatile("ldmatrix.sync.aligned.m8n8.x4.trans.shared.b16 {%0,%1,%2,%3}, [%4];"
        : "=r"(r[0]), "=r"(r[1]), "=r"(r[2]), "=r"(r[3]) : "r"(a));
}
// pack two floats to fp16x2 (satfinite); low half = p0, high half = p1
__device__ __forceinline__ uint32_t cvth2(float p0, float p1) {
    uint32_t r;
    asm("cvt.rn.satfinite.f16x2.f32 %0, %1, %2;" : "=r"(r) : "f"(p1), "f"(p0));
    return r;
}

// ---------------- adjacency bit-pack ----------------
__global__ void pack_adj_kernel(const int* __restrict__ A) {
    int gtid = blockIdx.x * blockDim.x + threadIdx.x;
    int gw   = gtid >> 5;
    int lane = gtid & 31;
    int wb   = gw * 32;
    if (wb >= NTOK * (NTOK / 32)) return;
    int row   = wb >> 7;
    int wcol0 = wb & 127;
    const int* ap = A + (size_t)row * NTOK + wcol0 * 32;
    unsigned mine = 0u;
#pragma unroll 8
    for (int k = 0; k < 32; k++) {
        unsigned b = __ballot_sync(0xffffffffu, ap[k * 32 + lane] > 0);
        if (lane == k) mine = b;
    }
    if (wcol0 + lane == (row >> 5)) mine |= 1u << (row & 31);
    g_adjb[wb + lane] = mine;
}

// ---------------- projection kernel -> fp16 planes [n][d] ----------------
#define XS_STR 68
#define PREP_SMEM_FLOATS (64 * XS_STR + 64 * 192)
#define PREP_SMEM_BYTES  (PREP_SMEM_FLOATS * 4)

__global__ __launch_bounds__(PT) void prep_kernel(
    const float* __restrict__ X, const float* __restrict__ W,
    const float* __restrict__ Q, const float* __restrict__ Kp)
{
    extern __shared__ float sm[];
    float* xs = sm;
    float* ws = sm + 64 * XS_STR;
    const int tid = threadIdx.x;
    const int g0  = blockIdx.x * 64;

    for (int idx = tid; idx < 64 * 16; idx += PT) {
        int r = idx >> 4, d4 = (idx & 15) << 2;
        float4 v = *(const float4*)(X + ((size_t)(g0 + r) << 6) + d4);
        xs[(d4 + 0) * XS_STR + r] = v.x;
        xs[(d4 + 1) * XS_STR + r] = v.y;
        xs[(d4 + 2) * XS_STR + r] = v.z;
        xs[(d4 + 3) * XS_STR + r] = v.w;
    }
    for (int idx = tid; idx < 64 * 48; idx += PT) {
        int d = idx / 48;
        int c4 = (idx % 48) << 2;
        const float* src;
        if (c4 < 64)       src = W  + d * 64 + c4;          // -> v
        else if (c4 < 128) src = Q  + d * 64 + (c4 - 64);   // -> q
        else               src = Kp + d * 64 + (c4 - 128);  // -> k
        *(float4*)(ws + d * 192 + c4) = *(const float4*)src;
    }
    __syncthreads();

    const int cg = tid % 24, rg = tid / 24;
    float acc[8][8];
#pragma unroll
    for (int i = 0; i < 8; i++)
#pragma unroll
        for (int j = 0; j < 8; j++) acc[i][j] = 0.f;

#pragma unroll 4
    for (int d = 0; d < 64; d++) {
        float4 a0 = *(const float4*)(xs + d * XS_STR + (rg << 3));
        float4 a1 = *(const float4*)(xs + d * XS_STR + (rg << 3) + 4);
        float4 w0 = *(const float4*)(ws + d * 192 + (cg << 3));
        float4 w1 = *(const float4*)(ws + d * 192 + (cg << 3) + 4);
        float a[8] = {a0.x, a0.y, a0.z, a0.w, a1.x, a1.y, a1.z, a1.w};
        float w[8] = {w0.x, w0.y, w0.z, w0.w, w1.x, w1.y, w1.z, w1.w};
#pragma unroll
        for (int i = 0; i < 8; i++)
#pragma unroll
            for (int j = 0; j < 8; j++) acc[i][j] += a[i] * w[j];
    }

    if (cg < 8) {
        // v: single fp16 plane
        int col0 = cg << 3;
#pragma unroll
        for (int i = 0; i < 8; i++) {
            size_t row = (size_t)(g0 + (rg << 3) + i);
            uint32_t w[4];
#pragma unroll
            for (int jp = 0; jp < 4; jp++)
                w[jp] = cvth2(acc[i][2 * jp], acc[i][2 * jp + 1]);
            *(uint4*)(g_v + row * 64 + col0) = make_uint4(w[0], w[1], w[2], w[3]);
        }
    } else {
        // q / k: fp16 hi + lo planes
        __half* gh = (cg < 16) ? g_qh : g_kh;
        __half* gl = (cg < 16) ? g_ql : g_kl;
        int col0 = ((cg < 16) ? (cg - 8) : (cg - 16)) << 3;
#pragma unroll
        for (int i = 0; i < 8; i++) {
            size_t row = (size_t)(g0 + (rg << 3) + i);
            uint32_t hw[4], lw[4];
#pragma unroll
            for (int jp = 0; jp < 4; jp++) {
                float f0 = acc[i][2 * jp], f1 = acc[i][2 * jp + 1];
                __half h0 = __float2half_rn(f0);
                __half h1 = __float2half_rn(f1);
                hw[jp] = (uint32_t)__half_as_ushort(h0) | ((uint32_t)__half_as_ushort(h1) << 16);
                lw[jp] = cvth2(f0 - __half2float(h0), f1 - __half2float(h1));
            }
            *(uint4*)(gh + row * 64 + col0) = make_uint4(hw[0], hw[1], hw[2], hw[3]);
            *(uint4*)(gl + row * 64 + col0) = make_uint4(lw[0], lw[1], lw[2], lw[3]);
        }
    }
}

// ---------------- mma.sync fused attention (fp16, 1-pass PV) ------------
// Double-buffered k/v, one barrier per iteration, online row-max softmax
// (fp16 P needs p<=1), per-lane partial l (scp is row-uniform in quad).
#define QH_OFF 0
#define QL_OFF 16384
#define KH_OFF 32768        // 2 x 8KB ring
#define KL_OFF 49152        // 2 x 8KB ring
#define V_OFF  65536        // 2 x 8KB ring
#define KV_STRIDE 8192
#define ATTN_SMEM_BYTES 81920

__global__ __launch_bounds__(AT, 2) void attn_kernel(float* __restrict__ out) {
    extern __shared__ char smc[];
    const uint32_t sb = s2u(smc);
    const int tid  = threadIdx.x;
    const int warp = tid >> 5;
    const int lane = tid & 31;
    const int q0   = blockIdx.x * BM;
    const int b    = blockIdx.y;

    const __half* qhb = g_qh + ((size_t)b << 18) + ((size_t)q0 << 6);
    const __half* qlb = g_ql + ((size_t)b << 18) + ((size_t)q0 << 6);
    const __half* khb = g_kh + ((size_t)b << 18);
    const __half* klb = g_kl + ((size_t)b << 18);
    const __half* vb  = g_v  + ((size_t)b << 18);

    // prologue: q both planes + k0/v0 into buffer 0, one group
#pragma unroll
    for (int it = 0; it < 8; it++) {
        int idx = tid + it * AT;           // 0..1023
        int r = idx >> 3, c = idx & 7;
        uint32_t doff = r * 128 + ((c ^ (r & 7)) << 4);
        cpa16(sb + QH_OFF + doff, qhb + r * 64 + c * 8);
        cpa16(sb + QL_OFF + doff, qlb + r * 64 + c * 8);
    }
#pragma unroll
    for (int it = 0; it < 4; it++) {
        int idx = tid + it * AT;           // 0..511
        int r = idx >> 3, c = idx & 7;
        uint32_t doff = r * 128 + ((c ^ (r & 7)) << 4);
        cpa16(sb + KH_OFF + doff, khb + r * 64 + c * 8);
        cpa16(sb + KL_OFF + doff, klb + r * 64 + c * 8);
        cpa16(sb + V_OFF  + doff, vb  + r * 64 + c * 8);
    }
    CP_COMMIT();

    // ldmatrix address invariants
    const int lr16 = lane & 15;
    const int lhi  = lane >> 4;            // 0/1
    uint32_t qa_off[2];
#pragma unroll
    for (int mt = 0; mt < 2; mt++) {
        int r = (warp << 5) + (mt << 4) + lr16;
        qa_off[mt] = (uint32_t)(r * 128) | ((uint32_t)(r & 7) << 28);
    }
    const int krow_b = (lhi << 3) + (lane & 7);
    const int kchalf = (lane >> 3) & 1;

    // accumulators / state
    float oacc[2][8][4];
    float m4[4], l4[4];
#pragma unroll
    for (int mt = 0; mt < 2; mt++)
#pragma unroll
        for (int nt = 0; nt < 8; nt++)
#pragma unroll
            for (int e = 0; e < 4; e++) oacc[mt][nt][e] = 0.f;
#pragma unroll
    for (int i = 0; i < 4; i++) { m4[i] = -1e30f; l4[i] = 0.f; }

    const float L2E = 1.4426950408889634f;
    const int cb = (lane & 3) << 1;

#pragma unroll 1
    for (int kt = 0; kt < KITER; kt++) {
        CP_WAIT(0);                        // k/v[kt] (+q on kt=0) arrived
        __syncthreads();                   // single barrier per iteration

        const uint32_t cur = (uint32_t)(kt & 1) * KV_STRIDE;
        const uint32_t nxt = KV_STRIDE - cur;

        // prefetch k/v[kt+1] into the other buffer
        if (kt + 1 < KITER) {
            const __half* kh2 = khb + (size_t)(kt + 1) * BN * 64;
            const __half* kl2 = klb + (size_t)(kt + 1) * BN * 64;
            const __half* v2  = vb  + (size_t)(kt + 1) * BN * 64;
#pragma unroll
            for (int it = 0; it < 4; it++) {
                int idx = tid + it * AT;
                int r = idx >> 3, c = idx & 7;
                uint32_t doff = r * 128 + ((c ^ (r & 7)) << 4);
                cpa16(sb + KH_OFF + nxt + doff, kh2 + r * 64 + c * 8);
                cpa16(sb + KL_OFF + nxt + doff, kl2 + r * 64 + c * 8);
                cpa16(sb + V_OFF  + nxt + doff, v2  + r * 64 + c * 8);
            }
        }
        CP_COMMIT();

        // adjacency words for this tile
        unsigned aw[4][2];
#pragma unroll
        for (int mt = 0; mt < 2; mt++)
#pragma unroll
            for (int dh = 0; dh < 2; dh++) {
                int rg_ = q0 + (warp << 5) + (mt << 4) + (dh << 3) + (lane >> 2);
                const unsigned* ap = g_adjb + ((size_t)rg_ << 7) + (kt << 1);
                aw[mt * 2 + dh][0] = __ldg(ap);
                aw[mt * 2 + dh][1] = __ldg(ap + 1);
            }

        // ---- QK: S = qh*kh + ql*kh + qh*kl (3-pass, fp16) ----
        float sacc[2][8][4];
#pragma unroll
        for (int mt = 0; mt < 2; mt++)
#pragma unroll
            for (int nt = 0; nt < 8; nt++)
#pragma unroll
                for (int e = 0; e < 4; e++) sacc[mt][nt][e] = 0.f;

#pragma unroll
        for (int ks = 0; ks < 4; ks++) {
            uint32_t aq[2][2][4];          // [plane][mt]
#pragma unroll
            for (int mt = 0; mt < 2; mt++) {
                uint32_t ro = qa_off[mt] & 0x0fffffffu;
                uint32_t sw = qa_off[mt] >> 28;
                uint32_t coff = (uint32_t)(((2 * ks + lhi) ^ sw) << 4);
                ldsm4(aq[0][mt], sb + QH_OFF + ro + coff);
                ldsm4(aq[1][mt], sb + QL_OFF + ro + coff);
            }
#pragma unroll
            for (int ntp = 0; ntp < 4; ntp++) {
                int rk = (ntp << 4) + krow_b;
                uint32_t doff = rk * 128 + ((uint32_t)(((2 * ks + kchalf) ^ (rk & 7))) << 4);
                uint32_t bh[4], bl[4];
                ldsm4(bh, sb + KH_OFF + cur + doff);
                ldsm4(bl, sb + KL_OFF + cur + doff);
#pragma unroll
                for (int mt = 0; mt < 2; mt++) {
                    mma16816(sacc[mt][2 * ntp],     aq[0][mt], bh);
                    mma16816(sacc[mt][2 * ntp + 1], aq[0][mt], bh + 2);
                    mma16816(sacc[mt][2 * ntp],     aq[1][mt], bh);
                    mma16816(sacc[mt][2 * ntp + 1], aq[1][mt], bh + 2);
                    mma16816(sacc[mt][2 * ntp],     aq[0][mt], bl);
                    mma16816(sacc[mt][2 * ntp + 1], aq[0][mt], bl + 2);
                }
            }
        }

        // ---- online softmax (row max via 2 quad shuffles); fp16 P ----
        uint32_t pha[2][4][4];
#pragma unroll
        for (int mt = 0; mt < 2; mt++)
#pragma unroll
            for (int dh = 0; dh < 2; dh++) {
                const int ri = mt * 2 + dh;
                float sv[16];
                int vbit[16];
                float mloc = -INFINITY;
#pragma unroll
                for (int nt = 0; nt < 8; nt++) {
                    unsigned w = aw[ri][nt >> 2];
                    const int sh = ((nt & 3) << 3) + cb;
#pragma unroll
                    for (int e = 0; e < 2; e++) {
                        float x = sacc[mt][nt][(dh << 1) + e];
                        x = fmaxf(x, 0.01f * x);
                        int bit = (int)((w >> (sh + e)) & 1u);
                        sv[nt * 2 + e] = x;
                        vbit[nt * 2 + e] = bit;
                        mloc = fmaxf(mloc, bit ? x : -INFINITY);
                    }
                }
                mloc = fmaxf(mloc, __shfl_xor_sync(0xffffffffu, mloc, 1));
                mloc = fmaxf(mloc, __shfl_xor_sync(0xffffffffu, mloc, 2));
                float mnew = fmaxf(m4[ri], mloc);
                float scp = ex2f((m4[ri] - mnew) * L2E);
                float mb = mnew * L2E;
                float rs = 0.f;
                float pv[16];
#pragma unroll
                for (int j = 0; j < 16; j++) {
                    float e2 = ex2f(fmaf(sv[j], L2E, -mb));
                    pv[j] = vbit[j] ? e2 : 0.f;
                    rs += pv[j];
                }
                l4[ri] = l4[ri] * scp + rs;   // per-lane partial (scp row-uniform)
                m4[ri] = mnew;
#pragma unroll
                for (int nt = 0; nt < 8; nt++) {
                    oacc[mt][nt][(dh << 1)]     *= scp;
                    oacc[mt][nt][(dh << 1) + 1] *= scp;
                }
#pragma unroll
                for (int nt = 0; nt < 8; nt++)
                    pha[mt][nt >> 1][(nt & 1) * 2 + dh] = cvth2(pv[nt * 2], pv[nt * 2 + 1]);
            }

        // ---- PV (1-pass): O += p * v  (fp16) ----
#pragma unroll
        for (int ks = 0; ks < 4; ks++) {
            int rv = (ks << 4) + lr16;
            uint32_t rbase = rv * 128;
            uint32_t rsw = rv & 7;
#pragma unroll
            for (int ntp = 0; ntp < 4; ntp++) {
                uint32_t coff = ((uint32_t)(((2 * ntp + lhi) ^ rsw)) << 4);
                uint32_t bv[4];
                ldsm4t(bv, sb + V_OFF + cur + rbase + coff);
#pragma unroll
                for (int mt = 0; mt < 2; mt++) {
                    mma16816(oacc[mt][2 * ntp],     pha[mt][ks], bv);
                    mma16816(oacc[mt][2 * ntp + 1], pha[mt][ks], bv + 2);
                }
            }
        }
    }

    // ---- epilogue: reduce l across lane quad ONCE, normalize, store ----
#pragma unroll
    for (int i = 0; i < 4; i++) {
        l4[i] += __shfl_xor_sync(0xffffffffu, l4[i], 1);
        l4[i] += __shfl_xor_sync(0xffffffffu, l4[i], 2);
    }
#pragma unroll
    for (int mt = 0; mt < 2; mt++)
#pragma unroll
        for (int dh = 0; dh < 2; dh++) {
            const int ri = mt * 2 + dh;
            float inv = 1.0f / l4[ri];
            int row_g = q0 + (warp << 5) + (mt << 4) + (dh << 3) + (lane >> 2);
            float* dst = out + ((size_t)(b * NTOK + row_g) << 6) + cb;
#pragma unroll
            for (int nt = 0; nt < 8; nt++) {
                float2 o2 = make_float2(oacc[mt][nt][(dh << 1)] * inv,
                                        oacc[mt][nt][(dh << 1) + 1] * inv);
                *(float2*)(dst + nt * 8) = o2;
            }
        }
}

// ---------------- launch ----------------
extern "C" void kernel_launch(void* const* d_in, const int* in_sizes, int n_in,
                              void* d_out, int out_size) {
    const float* X  = (const float*)d_in[0];
    const int*   A  = (const int*)  d_in[1];
    const float* W  = (const float*)d_in[2];
    const float* Q  = (const float*)d_in[3];
    const float* Kp = (const float*)d_in[4];
    float* out = (float*)d_out;

    cudaFuncSetAttribute(prep_kernel, cudaFuncAttributeMaxDynamicSharedMemorySize, PREP_SMEM_BYTES);
    cudaFuncSetAttribute(attn_kernel, cudaFuncAttributeMaxDynamicSharedMemorySize, ATTN_SMEM_BYTES);

    pack_adj_kernel<<<(NTOK * (NTOK / 32)) / 256, 256>>>(A);
    prep_kernel<<<(BATCH * NTOK) / 64, PT, PREP_SMEM_BYTES>>>(X, W, Q, Kp);
    attn_kernel<<<dim3(NTOK / BM, BATCH), AT, ATTN_SMEM_BYTES>>>(out);
}

// round 17
// speedup vs baseline: 1.7984x; 1.1259x over previous
#include <cuda_runtime.h>
#include <cuda_fp16.h>
#include <cstdint>
#include <cstddef>

typedef unsigned long long ull;

#define BATCH 8
#define NTOK  4096
#define DIM   64
#define BM    128
#define BN    64
#define KITER (NTOK / BN)
#define AT    128
#define PT    192

// ---------------- device scratch ----------------
__device__ __half g_q [BATCH * NTOK * DIM];  // [b][n][d] single fp16 plane
__device__ __half g_kh[BATCH * NTOK * DIM];  // k hi plane
__device__ __half g_kl[BATCH * NTOK * DIM];  // k lo plane (k = kh + kl, exact-ish)
__device__ __half g_v [BATCH * NTOK * DIM];  // single fp16 plane
__device__ unsigned g_adjb[NTOK * (NTOK / 32)];

// ---------------- helpers ----------------
__device__ __forceinline__ uint32_t s2u(const void* p) {
    return (uint32_t)__cvta_generic_to_shared(p);
}
__device__ __forceinline__ void cpa16(uint32_t dst, const void* src) {
    asm volatile("cp.async.cg.shared.global [%0], [%1], 16;" :: "r"(dst), "l"(src));
}
#define CP_COMMIT() asm volatile("cp.async.commit_group;")
#define CP_WAIT(n)  asm volatile("cp.async.wait_group %0;" :: "n"(n))
__device__ __forceinline__ float ex2f(float x) {
    float r; asm("ex2.approx.ftz.f32 %0, %1;" : "=f"(r) : "f"(x)); return r;
}
// fp16 mma m16n8k16, f32 accumulate
__device__ __forceinline__ void mma16816(float* d, const uint32_t* a, const uint32_t* b) {
    asm volatile("mma.sync.aligned.m16n8k16.row.col.f32.f16.f16.f32 "
        "{%0,%1,%2,%3}, {%4,%5,%6,%7}, {%8,%9}, {%0,%1,%2,%3};"
        : "+f"(d[0]), "+f"(d[1]), "+f"(d[2]), "+f"(d[3])
        : "r"(a[0]), "r"(a[1]), "r"(a[2]), "r"(a[3]), "r"(b[0]), "r"(b[1]));
}
__device__ __forceinline__ void ldsm4(uint32_t* r, uint32_t a) {
    asm volatile("ldmatrix.sync.aligned.m8n8.x4.shared.b16 {%0,%1,%2,%3}, [%4];"
        : "=r"(r[0]), "=r"(r[1]), "=r"(r[2]), "=r"(r[3]) : "r"(a));
}
__device__ __forceinline__ void ldsm4t(uint32_t* r, uint32_t a) {
    asm volatile("ldmatrix.sync.aligned.m8n8.x4.trans.shared.b16 {%0,%1,%2,%3}, [%4];"
        : "=r"(r[0]), "=r"(r[1]), "=r"(r[2]), "=r"(r[3]) : "r"(a));
}
// pack two floats to fp16x2 (satfinite); low half = p0, high half = p1
__device__ __forceinline__ uint32_t cvth2(float p0, float p1) {
    uint32_t r;
    asm("cvt.rn.satfinite.f16x2.f32 %0, %1, %2;" : "=r"(r) : "f"(p1), "f"(p0));
    return r;
}

// ---------------- adjacency bit-pack ----------------
__global__ void pack_adj_kernel(const int* __restrict__ A) {
    int gtid = blockIdx.x * blockDim.x + threadIdx.x;
    int gw   = gtid >> 5;
    int lane = gtid & 31;
    int wb   = gw * 32;
    if (wb >= NTOK * (NTOK / 32)) return;
    int row   = wb >> 7;
    int wcol0 = wb & 127;
    const int* ap = A + (size_t)row * NTOK + wcol0 * 32;
    unsigned mine = 0u;
#pragma unroll 8
    for (int k = 0; k < 32; k++) {
        unsigned b = __ballot_sync(0xffffffffu, ap[k * 32 + lane] > 0);
        if (lane == k) mine = b;
    }
    if (wcol0 + lane == (row >> 5)) mine |= 1u << (row & 31);
    g_adjb[wb + lane] = mine;
}

// ---------------- projection kernel -> fp16 planes [n][d] ----------------
#define XS_STR 68
#define PREP_SMEM_FLOATS (64 * XS_STR + 64 * 192)
#define PREP_SMEM_BYTES  (PREP_SMEM_FLOATS * 4)

__global__ __launch_bounds__(PT) void prep_kernel(
    const float* __restrict__ X, const float* __restrict__ W,
    const float* __restrict__ Q, const float* __restrict__ Kp)
{
    extern __shared__ float sm[];
    float* xs = sm;
    float* ws = sm + 64 * XS_STR;
    const int tid = threadIdx.x;
    const int g0  = blockIdx.x * 64;

    for (int idx = tid; idx < 64 * 16; idx += PT) {
        int r = idx >> 4, d4 = (idx & 15) << 2;
        float4 v = *(const float4*)(X + ((size_t)(g0 + r) << 6) + d4);
        xs[(d4 + 0) * XS_STR + r] = v.x;
        xs[(d4 + 1) * XS_STR + r] = v.y;
        xs[(d4 + 2) * XS_STR + r] = v.z;
        xs[(d4 + 3) * XS_STR + r] = v.w;
    }
    for (int idx = tid; idx < 64 * 48; idx += PT) {
        int d = idx / 48;
        int c4 = (idx % 48) << 2;
        const float* src;
        if (c4 < 64)       src = W  + d * 64 + c4;          // -> v
        else if (c4 < 128) src = Q  + d * 64 + (c4 - 64);   // -> q
        else               src = Kp + d * 64 + (c4 - 128);  // -> k
        *(float4*)(ws + d * 192 + c4) = *(const float4*)src;
    }
    __syncthreads();

    const int cg = tid % 24, rg = tid / 24;
    float acc[8][8];
#pragma unroll
    for (int i = 0; i < 8; i++)
#pragma unroll
        for (int j = 0; j < 8; j++) acc[i][j] = 0.f;

#pragma unroll 4
    for (int d = 0; d < 64; d++) {
        float4 a0 = *(const float4*)(xs + d * XS_STR + (rg << 3));
        float4 a1 = *(const float4*)(xs + d * XS_STR + (rg << 3) + 4);
        float4 w0 = *(const float4*)(ws + d * 192 + (cg << 3));
        float4 w1 = *(const float4*)(ws + d * 192 + (cg << 3) + 4);
        float a[8] = {a0.x, a0.y, a0.z, a0.w, a1.x, a1.y, a1.z, a1.w};
        float w[8] = {w0.x, w0.y, w0.z, w0.w, w1.x, w1.y, w1.z, w1.w};
#pragma unroll
        for (int i = 0; i < 8; i++)
#pragma unroll
            for (int j = 0; j < 8; j++) acc[i][j] += a[i] * w[j];
    }

    if (cg < 16) {
        // v (cg<8) and q (8<=cg<16): single fp16 plane
        __half* gp = (cg < 8) ? g_v : g_q;
        int col0 = ((cg < 8) ? cg : (cg - 8)) << 3;
#pragma unroll
        for (int i = 0; i < 8; i++) {
            size_t row = (size_t)(g0 + (rg << 3) + i);
            uint32_t w[4];
#pragma unroll
            for (int jp = 0; jp < 4; jp++)
                w[jp] = cvth2(acc[i][2 * jp], acc[i][2 * jp + 1]);
            *(uint4*)(gp + row * 64 + col0) = make_uint4(w[0], w[1], w[2], w[3]);
        }
    } else {
        // k: fp16 hi + lo planes (k kept exact across the two planes)
        int col0 = (cg - 16) << 3;
#pragma unroll
        for (int i = 0; i < 8; i++) {
            size_t row = (size_t)(g0 + (rg << 3) + i);
            uint32_t hw[4], lw[4];
#pragma unroll
            for (int jp = 0; jp < 4; jp++) {
                float f0 = acc[i][2 * jp], f1 = acc[i][2 * jp + 1];
                __half h0 = __float2half_rn(f0);
                __half h1 = __float2half_rn(f1);
                hw[jp] = (uint32_t)__half_as_ushort(h0) | ((uint32_t)__half_as_ushort(h1) << 16);
                lw[jp] = cvth2(f0 - __half2float(h0), f1 - __half2float(h1));
            }
            *(uint4*)(g_kh + row * 64 + col0) = make_uint4(hw[0], hw[1], hw[2], hw[3]);
            *(uint4*)(g_kl + row * 64 + col0) = make_uint4(lw[0], lw[1], lw[2], lw[3]);
        }
    }
}

// ---------------- mma.sync fused attention (fp16; 2-pass QK, 1-pass PV) --
// q single plane, k exact (hi+lo), v single plane. Double-buffered k/v,
// one barrier per iteration, online row-max softmax, per-lane partial l.
#define Q_OFF  0
#define KH_OFF 16384        // 2 x 8KB ring
#define KL_OFF 32768        // 2 x 8KB ring
#define V_OFF  49152        // 2 x 8KB ring
#define KV_STRIDE 8192
#define ATTN_SMEM_BYTES 65536

__global__ __launch_bounds__(AT, 2) void attn_kernel(float* __restrict__ out) {
    extern __shared__ char smc[];
    const uint32_t sb = s2u(smc);
    const int tid  = threadIdx.x;
    const int warp = tid >> 5;
    const int lane = tid & 31;
    const int q0   = blockIdx.x * BM;
    const int b    = blockIdx.y;

    const __half* qb  = g_q  + ((size_t)b << 18) + ((size_t)q0 << 6);
    const __half* khb = g_kh + ((size_t)b << 18);
    const __half* klb = g_kl + ((size_t)b << 18);
    const __half* vb  = g_v  + ((size_t)b << 18);

    // prologue: q + k0/v0 into buffer 0, one group
#pragma unroll
    for (int it = 0; it < 8; it++) {
        int idx = tid + it * AT;           // 0..1023
        int r = idx >> 3, c = idx & 7;
        uint32_t doff = r * 128 + ((c ^ (r & 7)) << 4);
        cpa16(sb + Q_OFF + doff, qb + r * 64 + c * 8);
    }
#pragma unroll
    for (int it = 0; it < 4; it++) {
        int idx = tid + it * AT;           // 0..511
        int r = idx >> 3, c = idx & 7;
        uint32_t doff = r * 128 + ((c ^ (r & 7)) << 4);
        cpa16(sb + KH_OFF + doff, khb + r * 64 + c * 8);
        cpa16(sb + KL_OFF + doff, klb + r * 64 + c * 8);
        cpa16(sb + V_OFF  + doff, vb  + r * 64 + c * 8);
    }
    CP_COMMIT();

    // ldmatrix address invariants
    const int lr16 = lane & 15;
    const int lhi  = lane >> 4;            // 0/1
    uint32_t qa_off[2];
#pragma unroll
    for (int mt = 0; mt < 2; mt++) {
        int r = (warp << 5) + (mt << 4) + lr16;
        qa_off[mt] = (uint32_t)(r * 128) | ((uint32_t)(r & 7) << 28);
    }
    const int krow_b = (lhi << 3) + (lane & 7);
    const int kchalf = (lane >> 3) & 1;

    // accumulators / state
    float oacc[2][8][4];
    float m4[4], l4[4];
#pragma unroll
    for (int mt = 0; mt < 2; mt++)
#pragma unroll
        for (int nt = 0; nt < 8; nt++)
#pragma unroll
            for (int e = 0; e < 4; e++) oacc[mt][nt][e] = 0.f;
#pragma unroll
    for (int i = 0; i < 4; i++) { m4[i] = -1e30f; l4[i] = 0.f; }

    const float L2E = 1.4426950408889634f;
    const int cb = (lane & 3) << 1;

#pragma unroll 1
    for (int kt = 0; kt < KITER; kt++) {
        CP_WAIT(0);                        // k/v[kt] (+q on kt=0) arrived
        __syncthreads();                   // single barrier per iteration

        const uint32_t cur = (uint32_t)(kt & 1) * KV_STRIDE;
        const uint32_t nxt = KV_STRIDE - cur;

        // prefetch k/v[kt+1] into the other buffer
        if (kt + 1 < KITER) {
            const __half* kh2 = khb + (size_t)(kt + 1) * BN * 64;
            const __half* kl2 = klb + (size_t)(kt + 1) * BN * 64;
            const __half* v2  = vb  + (size_t)(kt + 1) * BN * 64;
#pragma unroll
            for (int it = 0; it < 4; it++) {
                int idx = tid + it * AT;
                int r = idx >> 3, c = idx & 7;
                uint32_t doff = r * 128 + ((c ^ (r & 7)) << 4);
                cpa16(sb + KH_OFF + nxt + doff, kh2 + r * 64 + c * 8);
                cpa16(sb + KL_OFF + nxt + doff, kl2 + r * 64 + c * 8);
                cpa16(sb + V_OFF  + nxt + doff, v2  + r * 64 + c * 8);
            }
        }
        CP_COMMIT();

        // adjacency words for this tile
        unsigned aw[4][2];
#pragma unroll
        for (int mt = 0; mt < 2; mt++)
#pragma unroll
            for (int dh = 0; dh < 2; dh++) {
                int rg_ = q0 + (warp << 5) + (mt << 4) + (dh << 3) + (lane >> 2);
                const unsigned* ap = g_adjb + ((size_t)rg_ << 7) + (kt << 1);
                aw[mt * 2 + dh][0] = __ldg(ap);
                aw[mt * 2 + dh][1] = __ldg(ap + 1);
            }

        // ---- QK: S = q*kh^T + q*kl^T (2 passes, k exact) ----
        float sacc[2][8][4];
#pragma unroll
        for (int mt = 0; mt < 2; mt++)
#pragma unroll
            for (int nt = 0; nt < 8; nt++)
#pragma unroll
                for (int e = 0; e < 4; e++) sacc[mt][nt][e] = 0.f;

#pragma unroll
        for (int ks = 0; ks < 4; ks++) {
            uint32_t aq[2][4];
#pragma unroll
            for (int mt = 0; mt < 2; mt++) {
                uint32_t ro = qa_off[mt] & 0x0fffffffu;
                uint32_t sw = qa_off[mt] >> 28;
                uint32_t coff = (uint32_t)(((2 * ks + lhi) ^ sw) << 4);
                ldsm4(aq[mt], sb + Q_OFF + ro + coff);
            }
#pragma unroll
            for (int ntp = 0; ntp < 4; ntp++) {
                int rk = (ntp << 4) + krow_b;
                uint32_t doff = rk * 128 + ((uint32_t)(((2 * ks + kchalf) ^ (rk & 7))) << 4);
                uint32_t bh[4], bl[4];
                ldsm4(bh, sb + KH_OFF + cur + doff);
                ldsm4(bl, sb + KL_OFF + cur + doff);
#pragma unroll
                for (int mt = 0; mt < 2; mt++) {
                    mma16816(sacc[mt][2 * ntp],     aq[mt], bh);
                    mma16816(sacc[mt][2 * ntp + 1], aq[mt], bh + 2);
                    mma16816(sacc[mt][2 * ntp],     aq[mt], bl);
                    mma16816(sacc[mt][2 * ntp + 1], aq[mt], bl + 2);
                }
            }
        }

        // ---- online softmax (row max via 2 quad shuffles); fp16 P ----
        uint32_t pha[2][4][4];
#pragma unroll
        for (int mt = 0; mt < 2; mt++)
#pragma unroll
            for (int dh = 0; dh < 2; dh++) {
                const int ri = mt * 2 + dh;
                float sv[16];
                int vbit[16];
                float mloc = -INFINITY;
#pragma unroll
                for (int nt = 0; nt < 8; nt++) {
                    unsigned w = aw[ri][nt >> 2];
                    const int sh = ((nt & 3) << 3) + cb;
#pragma unroll
                    for (int e = 0; e < 2; e++) {
                        float x = sacc[mt][nt][(dh << 1) + e];
                        x = fmaxf(x, 0.01f * x);
                        int bit = (int)((w >> (sh + e)) & 1u);
                        sv[nt * 2 + e] = x;
                        vbit[nt * 2 + e] = bit;
                        mloc = fmaxf(mloc, bit ? x : -INFINITY);
                    }
                }
                mloc = fmaxf(mloc, __shfl_xor_sync(0xffffffffu, mloc, 1));
                mloc = fmaxf(mloc, __shfl_xor_sync(0xffffffffu, mloc, 2));
                float mnew = fmaxf(m4[ri], mloc);
                float scp = ex2f((m4[ri] - mnew) * L2E);
                float mb = mnew * L2E;
                float rs = 0.f;
                float pv[16];
#pragma unroll
                for (int j = 0; j < 16; j++) {
                    float e2 = ex2f(fmaf(sv[j], L2E, -mb));
                    pv[j] = vbit[j] ? e2 : 0.f;
                    rs += pv[j];
                }
                l4[ri] = l4[ri] * scp + rs;   // per-lane partial (scp row-uniform)
                m4[ri] = mnew;
#pragma unroll
                for (int nt = 0; nt < 8; nt++) {
                    oacc[mt][nt][(dh << 1)]     *= scp;
                    oacc[mt][nt][(dh << 1) + 1] *= scp;
                }
#pragma unroll
                for (int nt = 0; nt < 8; nt++)
                    pha[mt][nt >> 1][(nt & 1) * 2 + dh] = cvth2(pv[nt * 2], pv[nt * 2 + 1]);
            }

        // ---- PV (1 pass): O += p * v (fp16) ----
#pragma unroll
        for (int ks = 0; ks < 4; ks++) {
            int rv = (ks << 4) + lr16;
            uint32_t rbase = rv * 128;
            uint32_t rsw = rv & 7;
#pragma unroll
            for (int ntp = 0; ntp < 4; ntp++) {
                uint32_t coff = ((uint32_t)(((2 * ntp + lhi) ^ rsw)) << 4);
                uint32_t bv[4];
                ldsm4t(bv, sb + V_OFF + cur + rbase + coff);
#pragma unroll
                for (int mt = 0; mt < 2; mt++) {
                    mma16816(oacc[mt][2 * ntp],     pha[mt][ks], bv);
                    mma16816(oacc[mt][2 * ntp + 1], pha[mt][ks], bv + 2);
                }
            }
        }
    }

    // ---- epilogue: reduce l across lane quad ONCE, normalize, store ----
#pragma unroll
    for (int i = 0; i < 4; i++) {
        l4[i] += __shfl_xor_sync(0xffffffffu, l4[i], 1);
        l4[i] += __shfl_xor_sync(0xffffffffu, l4[i], 2);
    }
#pragma unroll
    for (int mt = 0; mt < 2; mt++)
#pragma unroll
        for (int dh = 0; dh < 2; dh++) {
            const int ri = mt * 2 + dh;
            float inv = 1.0f / l4[ri];
            int row_g = q0 + (warp << 5) + (mt << 4) + (dh << 3) + (lane >> 2);
            float* dst = out + ((size_t)(b * NTOK + row_g) << 6) + cb;
#pragma unroll
            for (int nt = 0; nt < 8; nt++) {
                float2 o2 = make_float2(oacc[mt][nt][(dh << 1)] * inv,
                                        oacc[mt][nt][(dh << 1) + 1] * inv);
                *(float2*)(dst + nt * 8) = o2;
            }
        }
}

// ---------------- launch ----------------
extern "C" void kernel_launch(void* const* d_in, const int* in_sizes, int n_in,
                              void* d_out, int out_size) {
    const float* X  = (const float*)d_in[0];
    const int*   A  = (const int*)  d_in[1];
    const float* W  = (const float*)d_in[2];
    const float* Q  = (const float*)d_in[3];
    const float* Kp = (const float*)d_in[4];
    float* out = (float*)d_out;

    cudaFuncSetAttribute(prep_kernel, cudaFuncAttributeMaxDynamicSharedMemorySize, PREP_SMEM_BYTES);
    cudaFuncSetAttribute(attn_kernel, cudaFuncAttributeMaxDynamicSharedMemorySize, ATTN_SMEM_BYTES);

    pack_adj_kernel<<<(NTOK * (NTOK / 32)) / 256, 256>>>(A);
    prep_kernel<<<(BATCH * NTOK) / 64, PT, PREP_SMEM_BYTES>>>(X, W, Q, Kp);
    attn_kernel<<<dim3(NTOK / BM, BATCH), AT, ATTN_SMEM_BYTES>>>(out);
}